// round 16
// baseline (speedup 1.0000x reference)
#include <cuda_runtime.h>
#include <cuda_fp16.h>
#include <cstdint>

#define NN 4000
#define SS 64
#define TT 12
#define K3S 192   // 3*SS
#define NCH 125   // 4000 / 32 n-chunks (k1)
#define KCH 24    // 768 / 32 k-chunks (k234)

// ------------------------- device scratch (no allocs) -------------------------
__device__ __align__(16) float g_h[NN * SS];
__device__ __align__(16) __half g_act_hi[(size_t)TT * NN * SS];
__device__ __align__(16) __half g_act_lo[(size_t)TT * NN * SS];
__device__ __align__(16) __half g_eB_hi[(size_t)TT * NCH * NN * 32];
__device__ __align__(16) int8_t g_eB_lo8[(size_t)TT * NCH * NN * 32];
__device__ __align__(16) float  g_eSc[(size_t)TT * NCH * NN];     // per (t,ci,m) lo scale
__device__ __align__(16) __half g_hB_hi[NCH * SS * 32];
__device__ __align__(16) int8_t g_hB_q[NCH * SS * 32];            // h quantized, scale 8/127
__device__ __align__(16) __half g_WT_hi[K3S * TT * SS];
__device__ __align__(16) __half g_WT_lo[K3S * TT * SS];

#define HQ_SCALE 15.875f          // 127/8
#define ESC_NORM (8.0f / 16129.0f) // 8 / 127^2

// ------------------------- helpers -------------------------
__device__ __forceinline__ uint32_t smem_u32(const void* p) {
    uint32_t a;
    asm("{ .reg .u64 t; cvta.to.shared.u64 t, %1; cvt.u32.u64 %0, t; }" : "=r"(a) : "l"(p));
    return a;
}
__device__ __forceinline__ void cp16(uint32_t dst, const void* src, int bytes) {
    asm volatile("cp.async.cg.shared.global [%0], [%1], 16, %2;" :: "r"(dst), "l"(src), "r"(bytes));
}
__device__ __forceinline__ void cp_commit() { asm volatile("cp.async.commit_group;"); }
__device__ __forceinline__ void cp_wait2()  { asm volatile("cp.async.wait_group 2;"); }
__device__ __forceinline__ void cp_wait1()  { asm volatile("cp.async.wait_group 1;"); }
__device__ __forceinline__ void cp_wait0()  { asm volatile("cp.async.wait_group 0;"); }

__device__ __forceinline__ void ldsm4(uint32_t& r0, uint32_t& r1, uint32_t& r2, uint32_t& r3,
                                      uint32_t addr) {
    asm volatile("ldmatrix.sync.aligned.m8n8.x4.shared.b16 {%0,%1,%2,%3}, [%4];"
                 : "=r"(r0), "=r"(r1), "=r"(r2), "=r"(r3) : "r"(addr));
}
__device__ __forceinline__ void mma16816(float* c, const uint32_t* a, const uint32_t* b) {
    asm volatile("mma.sync.aligned.m16n8k16.row.col.f32.f16.f16.f32 "
                 "{%0,%1,%2,%3}, {%4,%5,%6,%7}, {%8,%9}, {%0,%1,%2,%3};"
                 : "+f"(c[0]), "+f"(c[1]), "+f"(c[2]), "+f"(c[3])
                 : "r"(a[0]), "r"(a[1]), "r"(a[2]), "r"(a[3]), "r"(b[0]), "r"(b[1]));
}
__device__ __forceinline__ void imma16832(int* d, const uint32_t* a, const uint32_t* b) {
    asm volatile("mma.sync.aligned.m16n8k32.row.col.s32.s8.s8.s32 "
                 "{%0,%1,%2,%3}, {%4,%5,%6,%7}, {%8,%9}, {%10,%10,%10,%10};"
                 : "=r"(d[0]), "=r"(d[1]), "=r"(d[2]), "=r"(d[3])
                 : "r"(a[0]), "r"(a[1]), "r"(a[2]), "r"(a[3]),
                   "r"(b[0]), "r"(b[1]), "r"(0));
}
__device__ __forceinline__ uint32_t sw64(int r, uint32_t c) {
    return (uint32_t)(r * 64) + (c ^ (uint32_t)((r & 6) << 3));
}
__device__ __forceinline__ uint32_t pack_h2(float a, float b) {
    __half2 h = __floats2half2_rn(a, b);
    return *(uint32_t*)&h;
}
__device__ __forceinline__ uint16_t pack_q2(float a, float b) {
    int qa = (int)rintf(a), qb = (int)rintf(b);
    qa = max(-127, min(127, qa));
    qb = max(-127, min(127, qb));
    return (uint16_t)((qa & 0xFF) | ((qb & 0xFF) << 8));
}

// k1 stage layout
#define K1_AHI 0
#define K1_BHI 4096
#define K1_ALO 8192
#define K1_BLO 10240
#define K1_SC  12288
#define K1_STAGE 12544
#define P2_STAGE 28672   // k234: A 2K+2K | B 12K+12K

// =====================================================================
// setup: transpose + split E -> eB_hi fp16, eB_lo8 int8 + eSc scales
// =====================================================================
__global__ void __launch_bounds__(256) esplit(const float* __restrict__ e) {
    __shared__ float tile[256 * 33];
    const int t = blockIdx.z;
    const int ci = blockIdx.y;
    const int n0 = ci * 32;
    const int m0 = blockIdx.x * 256;
    const int tid = threadIdx.x;
    const float* eb = e + (size_t)t * NN * NN;

#pragma unroll
    for (int j = 0; j < 8; j++) {
        const int idx = tid + 256 * j;
        const int r = idx >> 6;
        const int c4 = idx & 63;
        const int m = m0 + c4 * 4;
        float4 v = make_float4(0.f, 0.f, 0.f, 0.f);
        if (m < NN) v = *(const float4*)(eb + (size_t)(n0 + r) * NN + m);
        const int ml = c4 * 4;
        tile[(ml + 0) * 33 + r] = v.x;
        tile[(ml + 1) * 33 + r] = v.y;
        tile[(ml + 2) * 33 + r] = v.z;
        tile[(ml + 3) * 33 + r] = v.w;
    }
    __syncthreads();

    const size_t rowbase = ((size_t)t * NCH + ci) * NN;
    const int px = tid & 15;
    const int my = tid >> 4;
#pragma unroll
    for (int p = 0; p < 16; p++) {
        const int ml = p * 16 + my;
        const int m = m0 + ml;
        const bool valid = (m < NN);
        const float v0 = tile[ml * 33 + 2 * px];
        const float v1 = tile[ml * 33 + 2 * px + 1];
        const float h0 = __half2float(__float2half_rn(v0));
        const float h1 = __half2float(__float2half_rn(v1));
        const float e0 = v0 - h0, e1 = v1 - h1;
        // group max of |Elo| over the 32-n chunk (16-lane subgroup reduction)
        float gm = fmaxf(fabsf(e0), fabsf(e1));
        gm = fmaxf(gm, __shfl_xor_sync(0xffffffffu, gm, 1));
        gm = fmaxf(gm, __shfl_xor_sync(0xffffffffu, gm, 2));
        gm = fmaxf(gm, __shfl_xor_sync(0xffffffffu, gm, 4));
        gm = fmaxf(gm, __shfl_xor_sync(0xffffffffu, gm, 8));
        gm = fmaxf(gm, 1e-20f);
        const float inv = 127.0f / gm;
        if (valid) {
            const size_t o = (rowbase + m) * 32 + 2 * px;
            *(uint32_t*)&g_eB_hi[o] = pack_h2(v0, v1);
            *(uint16_t*)&g_eB_lo8[o] = pack_q2(e0 * inv, e1 * inv);
            if (px == 0) g_eSc[rowbase + m] = gm * ESC_NORM;
        }
    }
}

// one-time: W^T split  WT[n][k] = W[k/64][k%64][n]
__global__ void __launch_bounds__(256) wsplit(const float* __restrict__ W) {
    const int idx = blockIdx.x * 256 + threadIdx.x;
    if (idx >= K3S * TT * SS) return;
    const int n = idx / (TT * SS);
    const int k = idx - n * (TT * SS);
    const float v = W[(size_t)k * K3S + n];
    const __half hi = __float2half_rn(v);
    g_WT_hi[idx] = hi;
    g_WT_lo[idx] = __float2half_rn(v - __half2float(hi));
}

// once before loop: transpose h -> hB_hi fp16 + hB_q int8
__global__ void __launch_bounds__(256) hsplit(const int* __restrict__ iters, int it_idx) {
    if (it_idx >= *iters) return;
    __shared__ float tile[32][33];
    const int n0 = blockIdx.x * 32;
    const int ci = n0 >> 5;
    const int s0 = blockIdx.y * 32;
    const int tx = threadIdx.x & 31;
    const int ty = threadIdx.x >> 5;
#pragma unroll
    for (int i = 0; i < 4; i++) {
        const int n = n0 + ty + i * 8;
        tile[ty + i * 8][tx] = g_h[(size_t)n * SS + s0 + tx];
    }
    __syncthreads();
#pragma unroll
    for (int i = 0; i < 4; i++) {
        const int s = s0 + ty + i * 8;
        const float v = tile[tx][ty + i * 8];
        const size_t o = ((size_t)ci * SS + s) * 32 + tx;
        g_hB_hi[o] = __float2half_rn(v);
        int q = (int)rintf(v * HQ_SCALE);
        q = max(-127, min(127, q));
        g_hB_q[o] = (int8_t)q;
    }
}

// =====================================================================
// K1 (HMMA+IMMA): act = E^T h + ba -> fp16 hi/lo
// hi product fp16 (Ehi*Hhi), lo product int8 IMMA (Elo8*Hq, per-chunk rescale).
// m-tile 64: grid (63, 12), block 256 (2 m32 x 4 s16 warps). 4-stage x 12.25KB.
// =====================================================================
__device__ __forceinline__ void k1_load_chunk(int tid, int t, int m0, int ci, uint32_t smem) {
    const uint32_t base = smem + (uint32_t)(ci & 3) * K1_STAGE;
    const size_t arow = ((size_t)t * NCH + ci) * NN;
    {   // A hi: 64 rows x 4 x 16B
        const int r = tid >> 2, c16 = tid & 3;
        const int m = m0 + r;
        const int ok = (m < NN) ? 16 : 0;
        const int mc = (m < NN) ? m : (NN - 1);
        cp16(base + K1_AHI + sw64(r, (uint32_t)(c16 * 16)),
             g_eB_hi + (arow + mc) * 32 + c16 * 8, ok);
        // B hi: 64 rows x 4 x 16B
        cp16(base + K1_BHI + sw64(r, (uint32_t)(c16 * 16)),
             g_hB_hi + ((size_t)ci * SS + r) * 32 + c16 * 8, 16);
    }
    if (tid < 128) {  // A lo8: 64 rows x 2 x 16B
        const int r = tid >> 1, c = tid & 1;
        const int m = m0 + r;
        const int ok = (m < NN) ? 16 : 0;
        const int mc = (m < NN) ? m : (NN - 1);
        const uint32_t dst = base + K1_ALO + (uint32_t)(r * 32) + (uint32_t)((c ^ (r & 1)) * 16);
        cp16(dst, g_eB_lo8 + (arow + mc) * 32 + c * 16, ok);
    } else {          // B lo8: 64 rows x 2 x 16B
        const int rt = tid - 128;
        const int r = rt >> 1, c = rt & 1;
        const uint32_t dst = base + K1_BLO + (uint32_t)(r * 32) + (uint32_t)((c ^ (r & 1)) * 16);
        cp16(dst, g_hB_q + ((size_t)ci * SS + r) * 32 + c * 16, 16);
    }
    if (tid < 16) {   // sc: 64 floats
        const int m = m0 + tid * 4;
        const int ok = (m < NN) ? 16 : 0;
        cp16(base + K1_SC + (uint32_t)(tid * 16), g_eSc + arow + m, ok);
    }
    cp_commit();
}

__global__ void __launch_bounds__(256) k1_hmma(const float* __restrict__ ba,
                                               const int* __restrict__ iters, int it_idx) {
    if (it_idx >= *iters) return;
    extern __shared__ char dsm[];
    const int tid = threadIdx.x;
    const int wid = tid >> 5;
    const int lid = tid & 31;
    const int tt = blockIdx.y;
    const int m0 = blockIdx.x * 64;
    const uint32_t smem = smem_u32(dsm);

    const int wm = wid & 1;      // m32 block
    const int ws = wid >> 1;     // s16 block

    float acc[2][2][4];
#pragma unroll
    for (int a = 0; a < 2; a++)
#pragma unroll
        for (int b = 0; b < 2; b++)
#pragma unroll
            for (int j = 0; j < 4; j++) acc[a][b][j] = 0.f;

    const int arow = wm * 32 + (lid & 15);                      // + a*16
    const uint32_t abyt = (uint32_t)((lid >> 4) << 4);
    const int brow0 = ws * 16 + ((lid >> 4) << 3) + (lid & 7);
    const uint32_t bbyt = (uint32_t)(((lid >> 3) & 1) << 4);
    const int srow = (lid >> 2);                                // c-frag row within 8

    k1_load_chunk(tid, tt, m0, 0, smem);
    k1_load_chunk(tid, tt, m0, 1, smem);
    k1_load_chunk(tid, tt, m0, 2, smem);

    for (int ci = 0; ci < NCH; ci++) {
        if (ci + 2 < NCH) cp_wait2();
        else if (ci + 1 < NCH) cp_wait1();
        else cp_wait0();
        __syncthreads();

        const uint32_t base = smem + (uint32_t)(ci & 3) * K1_STAGE;
        // ---- hi product: fp16, two K=16 halves ----
#pragma unroll
        for (int kk = 0; kk < 2; kk++) {
            const uint32_t kb = (uint32_t)(kk * 32);
            uint32_t ah[2][4], bh[4];
#pragma unroll
            for (int a = 0; a < 2; a++) {
                const int r = arow + a * 16;
                const uint32_t ad = base + K1_AHI + (uint32_t)(r * 64) + ((kb + abyt) ^ (uint32_t)((r & 6) << 3));
                ldsm4(ah[a][0], ah[a][1], ah[a][2], ah[a][3], ad);
            }
            {
                const int r = brow0;
                const uint32_t bd = base + K1_BHI + (uint32_t)(r * 64) + ((kb + bbyt) ^ (uint32_t)((r & 6) << 3));
                ldsm4(bh[0], bh[1], bh[2], bh[3], bd);
            }
#pragma unroll
            for (int a = 0; a < 2; a++)
#pragma unroll
                for (int b = 0; b < 2; b++) {
                    uint32_t bfh[2] = { bh[b * 2], bh[b * 2 + 1] };
                    mma16816(acc[a][b], ah[a], bfh);
                }
        }
        // ---- lo product: int8 IMMA, K=32 in one shot ----
        {
            uint32_t aq[2][4], bq[4];
#pragma unroll
            for (int a = 0; a < 2; a++) {
                const int r = arow + a * 16;
                const uint32_t ad = base + K1_ALO + (uint32_t)(r * 32) + (abyt ^ (uint32_t)((r & 1) << 4));
                ldsm4(aq[a][0], aq[a][1], aq[a][2], aq[a][3], ad);
            }
            {
                const int r = brow0;
                const uint32_t bd = base + K1_BLO + (uint32_t)(r * 32) + (bbyt ^ (uint32_t)((r & 1) << 4));
                ldsm4(bq[0], bq[1], bq[2], bq[3], bd);
            }
            const float* scs = (const float*)(dsm + (size_t)(ci & 3) * K1_STAGE + K1_SC);
#pragma unroll
            for (int a = 0; a < 2; a++) {
                const float sc0 = scs[wm * 32 + a * 16 + srow];
                const float sc1 = scs[wm * 32 + a * 16 + srow + 8];
#pragma unroll
                for (int b = 0; b < 2; b++) {
                    uint32_t bf[2] = { bq[b * 2], bq[b * 2 + 1] };
                    int d[4];
                    imma16832(d, aq[a], bf);
                    acc[a][b][0] += (float)d[0] * sc0;
                    acc[a][b][1] += (float)d[1] * sc0;
                    acc[a][b][2] += (float)d[2] * sc1;
                    acc[a][b][3] += (float)d[3] * sc1;
                }
            }
        }
        if (ci + 3 < NCH) k1_load_chunk(tid, tt, m0, ci + 3, smem);
    }

#pragma unroll
    for (int b = 0; b < 2; b++) {
        const int scol = ws * 16 + b * 8 + (lid & 3) * 2;
        const float2 bav = *(const float2*)(ba + tt * SS + scol);
#pragma unroll
        for (int a = 0; a < 2; a++) {
            const int mrow = m0 + wm * 32 + a * 16 + (lid >> 2);
#pragma unroll
            for (int half8 = 0; half8 < 2; half8++) {
                const int mr = mrow + half8 * 8;
                if (mr < NN) {
                    const float ox = acc[a][b][half8 * 2 + 0] + bav.x;
                    const float oy = acc[a][b][half8 * 2 + 1] + bav.y;
                    const float hx = __half2float(__float2half_rn(ox));
                    const float hy = __half2float(__float2half_rn(oy));
                    const size_t o = ((size_t)tt * NN + mr) * SS + scol;
                    *(uint32_t*)&g_act_hi[o] = pack_h2(ox, oy);
                    *(uint32_t*)&g_act_lo[o] = pack_h2(ox - hx, oy - hy);
                }
            }
        }
    }
}

// =====================================================================
// K234 (fused): per 32-row m-chunk (grid 125): aw GEMM (3-product) in smem,
// then GRU + hB_hi/hB_q transpose-write.
// =====================================================================
#define P2_U    0
#define P2_PIPE 49152
#define P2_DSM  (49152 + 3 * P2_STAGE)   // 135168

__device__ __forceinline__ void k234_load_chunk(int tid, int m0, int ci, uint32_t smem) {
    const uint32_t base = smem + P2_PIPE + (uint32_t)(ci % 3) * P2_STAGE;
    const int t = ci >> 1;
    const int sh = (ci & 1) * 32;
    if (tid < 128) {
        const int r = tid >> 2, c16 = tid & 3;
        const int m = m0 + r;
        const uint32_t sw = sw64(r, (uint32_t)(c16 * 16));
        const size_t off = ((size_t)t * NN + m) * SS + sh + c16 * 8;
        cp16(base + sw,        g_act_hi + off, 16);
        cp16(base + 2048 + sw, g_act_lo + off, 16);
    }
#pragma unroll
    for (int q = 0; q < 3; q++) {
        const int idx = tid + 256 * q;
        const int r = idx >> 2, c16 = idx & 3;
        const uint32_t sw = sw64(r, (uint32_t)(c16 * 16));
        const size_t off = (size_t)r * (TT * SS) + t * SS + sh + c16 * 8;
        cp16(base + 4096 + sw,  g_WT_hi + off, 16);
        cp16(base + 16384 + sw, g_WT_lo + off, 16);
    }
    cp_commit();
}

__global__ void __launch_bounds__(256) k234_fused(const float* __restrict__ bw,
                                                  const float* __restrict__ uz_ur,
                                                  const float* __restrict__ uh,
                                                  const int* __restrict__ iters, int it_idx) {
    if (it_idx >= *iters) return;
    extern __shared__ char dsm[];
    const int tid = threadIdx.x;
    const int wid = tid >> 5;
    const int lid = tid & 31;
    const int cib = blockIdx.x;
    const int m0 = cib * 32;
    const uint32_t smem = smem_u32(dsm);

#pragma unroll
    for (int i = 0; i < 8; i++)
        cp16(smem + P2_U + (uint32_t)(tid + 256 * i) * 16,
             (const char*)uz_ur + (size_t)(tid + 256 * i) * 16, 16);
#pragma unroll
    for (int i = 0; i < 4; i++)
        cp16(smem + P2_U + 32768 + (uint32_t)(tid + 256 * i) * 16,
             (const char*)uh + (size_t)(tid + 256 * i) * 16, 16);
    cp_commit();

    const int wm = wid & 1;
    const int wn = wid >> 1;

    float acc[6][4];
#pragma unroll
    for (int b = 0; b < 6; b++)
#pragma unroll
        for (int j = 0; j < 4; j++) acc[b][j] = 0.f;

    const int arow = wm * 16 + (lid & 15);
    const uint32_t abyt = (uint32_t)((lid >> 4) << 4);
    const int brow0 = wn * 48 + ((lid >> 4) << 3) + (lid & 7);
    const uint32_t bbyt = (uint32_t)(((lid >> 3) & 1) << 4);

    k234_load_chunk(tid, m0, 0, smem);
    k234_load_chunk(tid, m0, 1, smem);
    k234_load_chunk(tid, m0, 2, smem);

    for (int ci = 0; ci < KCH; ci++) {
        if (ci + 2 < KCH) cp_wait2();
        else if (ci + 1 < KCH) cp_wait1();
        else cp_wait0();
        __syncthreads();

        const uint32_t base = smem + P2_PIPE + (uint32_t)(ci % 3) * P2_STAGE;
#pragma unroll
        for (int kk = 0; kk < 2; kk++) {
            const uint32_t kb = (uint32_t)(kk * 32);
            uint32_t ah[4], al[4], bh[3][4], bl[3][4];
            {
                const int r = arow;
                const uint32_t ad = base + (uint32_t)(r * 64) + ((kb + abyt) ^ (uint32_t)((r & 6) << 3));
                ldsm4(ah[0], ah[1], ah[2], ah[3], ad);
                ldsm4(al[0], al[1], al[2], al[3], ad + 2048);
            }
#pragma unroll
            for (int bp = 0; bp < 3; bp++) {
                const int r = brow0 + bp * 16;
                const uint32_t bd = base + 4096 + (uint32_t)(r * 64) + ((kb + bbyt) ^ (uint32_t)((r & 6) << 3));
                ldsm4(bh[bp][0], bh[bp][1], bh[bp][2], bh[bp][3], bd);
                ldsm4(bl[bp][0], bl[bp][1], bl[bp][2], bl[bp][3], bd + 12288);
            }
#pragma unroll
            for (int b = 0; b < 6; b++) {
                uint32_t bfh[2] = { bh[b >> 1][(b & 1) * 2], bh[b >> 1][(b & 1) * 2 + 1] };
                uint32_t bfl[2] = { bl[b >> 1][(b & 1) * 2], bl[b >> 1][(b & 1) * 2 + 1] };
                mma16816(acc[b], ah, bfh);
                mma16816(acc[b], al, bfh);
                mma16816(acc[b], ah, bfl);
            }
        }
        if (ci + 3 < KCH) k234_load_chunk(tid, m0, ci + 3, smem);
    }
    __syncthreads();

    float* aw_s = (float*)(dsm + P2_PIPE);                 // [32][200]
    float* shh  = (float*)(dsm + P2_PIPE + 25600);         // [32][65]
    float* srh  = shh + 32 * 65;                           // [32][64]
    float* sz   = srh + 32 * 64;                           // [32][64]
    const float* sUZ = (const float*)(dsm + P2_U);         // [64][128]
    const float* sUH = (const float*)(dsm + P2_U + 32768); // [64][64]

#pragma unroll
    for (int b = 0; b < 6; b++) {
        const int col = wn * 48 + b * 8 + (lid & 3) * 2;
        const int r0 = wm * 16 + (lid >> 2);
        *(float2*)&aw_s[r0 * 200 + col]       = make_float2(acc[b][0], acc[b][1]);
        *(float2*)&aw_s[(r0 + 8) * 200 + col] = make_float2(acc[b][2], acc[b][3]);
    }
#pragma unroll
    for (int j = 0; j < 8; j++) {
        const int idx = tid + 256 * j;
        const int r = idx >> 6, s = idx & 63;
        shh[r * 65 + s] = g_h[(size_t)(m0 + r) * SS + s];
    }
    __syncthreads();

    const int tx = tid & 15, ty = tid >> 4;
    {
        const int k0 = tx * 8;
#pragma unroll
        for (int rr = 0; rr < 2; rr++) {
            const int r = ty + rr * 16;
            float accv[8] = {0.f, 0.f, 0.f, 0.f, 0.f, 0.f, 0.f, 0.f};
#pragma unroll 8
            for (int s = 0; s < 64; s++) {
                const float hv = shh[r * 65 + s];
#pragma unroll
                for (int j = 0; j < 8; j++) accv[j] += hv * sUZ[s * 128 + k0 + j];
            }
#pragma unroll
            for (int j = 0; j < 8; j++) {
                const int k = k0 + j;
                const float gt = aw_s[r * 200 + k] + 12.0f * bw[k] + accv[j];
                const float sg = 1.0f / (1.0f + __expf(-gt));
                if (k < 64) sz[r * 64 + k] = sg;
                else        srh[r * 64 + (k - 64)] = sg * shh[r * 65 + (k - 64)];
            }
        }
    }
    __syncthreads();
    {
        const int k0 = tx * 4;
#pragma unroll
        for (int rr = 0; rr < 2; rr++) {
            const int r = ty + rr * 16;
            const int m = m0 + r;
            float accv[4] = {0.f, 0.f, 0.f, 0.f};
#pragma unroll 8
            for (int s = 0; s < 64; s++) {
                const float rv = srh[r * 64 + s];
#pragma unroll
                for (int j = 0; j < 4; j++) accv[j] += rv * sUH[s * 64 + k0 + j];
            }
#pragma unroll
            for (int j = 0; j < 4; j++) {
                const int k = k0 + j;
                const float hhv = tanhf(aw_s[r * 200 + 128 + k] + 12.0f * bw[128 + k] + accv[j]);
                const float zv = sz[r * 64 + k];
                const float hv = shh[r * 65 + k];
                const float hnew = (1.0f - zv) * hv + zv * hhv;
                g_h[(size_t)m * SS + k] = hnew;
                shh[r * 65 + k] = hnew;
            }
        }
    }
    __syncthreads();
    {   // hB_hi + hB_q transpose-write for next iteration's k1
        const int pr = tid & 15;
        const int sb = tid >> 4;
#pragma unroll
        for (int j = 0; j < 4; j++) {
            const int s = sb + 16 * j;
            const float v0 = shh[(2 * pr) * 65 + s];
            const float v1 = shh[(2 * pr + 1) * 65 + s];
            const size_t o = ((size_t)cib * SS + s) * 32 + 2 * pr;
            *(uint32_t*)&g_hB_hi[o] = pack_h2(v0, v1);
            *(uint16_t*)&g_hB_q[o] = pack_q2(v0 * HQ_SCALE, v1 * HQ_SCALE);
        }
    }
}

// ---- copies ----
__global__ void kcopy_in(const float* __restrict__ x) {
    const int i = blockIdx.x * 256 + threadIdx.x;
    if (i < NN * SS) g_h[i] = x[i];
}
__global__ void kcopy_out(float* __restrict__ out) {
    const int i = blockIdx.x * 256 + threadIdx.x;
    if (i < NN * SS) out[i] = g_h[i];
}

extern "C" void kernel_launch(void* const* d_in, const int* in_sizes, int n_in,
                              void* d_out, int out_size) {
    const float* x     = (const float*)d_in[0];
    const float* e     = (const float*)d_in[1];
    const float* ba    = (const float*)d_in[2];
    const float* bw    = (const float*)d_in[3];
    const float* W     = (const float*)d_in[4];
    const float* uz_ur = (const float*)d_in[5];
    const float* uh    = (const float*)d_in[6];
    const int*   iters = (const int*)d_in[7];
    float* out = (float*)d_out;

    cudaFuncSetAttribute(k1_hmma, cudaFuncAttributeMaxDynamicSharedMemorySize, 4 * K1_STAGE);
    cudaFuncSetAttribute(k1_hmma, cudaFuncAttributePreferredSharedMemoryCarveout, 100);
    cudaFuncSetAttribute(k234_fused, cudaFuncAttributeMaxDynamicSharedMemorySize, P2_DSM);
    cudaFuncSetAttribute(k234_fused, cudaFuncAttributePreferredSharedMemoryCarveout, 100);

    const int cpb = (NN * SS + 255) / 256;
    kcopy_in<<<cpb, 256>>>(x);

    dim3 ge(16, NCH, TT);
    esplit<<<ge, 256>>>(e);
    wsplit<<<(K3S * TT * SS + 255) / 256, 256>>>(W);

    const dim3 gh(NN / 32, SS / 32);
    hsplit<<<gh, 256>>>(iters, 0);   // hB for iteration 0; k234 maintains it after

    const dim3 g1((NN + 63) / 64, TT);

    for (int it = 0; it < 10; it++) {
        k1_hmma<<<g1, 256, 4 * K1_STAGE>>>(ba, iters, it);
        k234_fused<<<NCH, 256, P2_DSM>>>(bw, uz_ur, uh, iters, it);
    }

    kcopy_out<<<cpb, 256>>>(out);
}